// round 7
// baseline (speedup 1.0000x reference)
#include <cuda_runtime.h>

#define DD  512
#define KK  16
#define RPB 128            // rows per block
#define TPB 256            // threads per block
#define CH  16             // dims per staged chunk
#define NCH (DD/CH)        // 32 chunks
#define F4C (CH/4)         // 4 float4 per row per chunk

// ---- device scratch (no allocations allowed) ----
__device__ float g_bsum[4096];
__device__ unsigned int g_done = 0;

// ---- packed f32x2 helpers (Blackwell FFMA2) ----
__device__ __forceinline__ void upk2(unsigned long long v, float& lo, float& hi) {
    asm("mov.b64 {%0,%1}, %2;" : "=f"(lo), "=f"(hi) : "l"(v));
}
__device__ __forceinline__ unsigned long long ffma2(unsigned long long a,
                                                    unsigned long long b,
                                                    unsigned long long c) {
    unsigned long long d;
    asm("fma.rn.f32x2 %0, %1, %2, %3;" : "=l"(d) : "l"(a), "l"(b), "l"(c));
    return d;
}
__device__ __forceinline__ void cpasync16(unsigned dst, const void* src) {
    asm volatile("cp.async.cg.shared.global [%0], [%1], 16;" :: "r"(dst), "l"(src) : "memory");
}

__global__ void __launch_bounds__(TPB, 4) vq_fused(
    const float* __restrict__ z, const float* __restrict__ cb,
    float* __restrict__ zq, float* __restrict__ idxp, float* __restrict__ lossp,
    int nrows, int nblocks, float scale)
{
    __shared__ float      sc[KK * DD];          // 32 KB codebook
    __shared__ ulonglong2 zs[2][F4C * RPB];     // 2 x 8 KB z staging (double buffer)
    __shared__ float      c2s[KK];
    __shared__ float      sdist[2][RPB];        // per-half best dist (reused as loss partials)
    __shared__ int        sidx[2][RPB];         // per-half best idx  ([0] reused as final idx)
    __shared__ unsigned int ticket;

    const int t = threadIdx.x;
    const int w = t >> 5, lane = t & 31;
    const int half  = w & 1;                    // k-half this warp owns
    const int khalf = half * 8;
    const int row   = ((w >> 1) << 5) + lane;   // this thread's block-local row (0..127)
    const int rowbase = blockIdx.x * RPB;

    const unsigned zs_sa = (unsigned)__cvta_generic_to_shared(zs);

    const int jj = t & 3;                       // staging role: float4-slot
    const int rl = t >> 2;                      // staging role: row (0..63)
    const int lastrow = nrows - 1;

    // ---- cp.async chunk 0 (2 x 16B per thread) ----
    #pragma unroll
    for (int i = 0; i < 2; i++) {
        int rr = rl + 64 * i;
        int gr = rowbase + rr; if (gr > lastrow) gr = lastrow;
        const char* src = (const char*)z + ((size_t)gr * (DD / 4) + jj) * 16;
        unsigned dst = zs_sa + (unsigned)((jj * RPB + (rr ^ jj)) * 16);
        cpasync16(dst, src);
    }
    asm volatile("cp.async.commit_group;" ::: "memory");

    // ---- stage codebook (coalesced float4) ----
    for (int i = t; i < KK * DD / 4; i += TPB)
        ((float4*)sc)[i] = ((const float4*)cb)[i];
    __syncthreads();

    // ---- codebook squared norms (identical per-k arithmetic to passing kernel) ----
    #pragma unroll
    for (int kk = 0; kk < 2; kk++) {
        int k = w * 2 + kk;
        float s = 0.f;
        for (int j = lane; j < DD; j += 32) {
            float v = sc[k * DD + j];
            s = fmaf(v, v, s);
        }
        #pragma unroll
        for (int o = 16; o; o >>= 1) s += __shfl_xor_sync(0xffffffffu, s, o);
        if (lane == 0) c2s[k] = s;
    }

    // ---- split accumulators: 8 k x 2 chains for ONE row ----
    unsigned long long acc0[8], acc1[8];
    #pragma unroll
    for (int k = 0; k < 8; k++) { acc0[k] = 0ull; acc1[k] = 0ull; }
    unsigned long long z2a = 0ull, z2b = 0ull;

    for (int c = 0; c < NCH; c++) {
        asm volatile("cp.async.wait_group 0;" ::: "memory");
        __syncthreads();                 // chunk c visible; previous buffer free

        if (c + 1 < NCH) {               // prefetch next chunk into the other buffer
            #pragma unroll
            for (int i = 0; i < 2; i++) {
                int rr = rl + 64 * i;
                int gr = rowbase + rr; if (gr > lastrow) gr = lastrow;
                const char* src = (const char*)z +
                    ((size_t)gr * (DD / 4) + (size_t)(c + 1) * F4C + jj) * 16;
                unsigned dst = zs_sa +
                    (unsigned)((((c + 1) & 1) * F4C * RPB + jj * RPB + (rr ^ jj)) * 16);
                cpasync16(dst, src);
            }
            asm volatile("cp.async.commit_group;" ::: "memory");
        }

        const ulonglong2* zbuf = zs[c & 1];
        const float* cbb = sc + (khalf * DD + c * CH);

        #pragma unroll
        for (int j = 0; j < F4C; j++) {
            ulonglong2 zv = zbuf[j * RPB + (row ^ j)];   // .x=(x,y) .y=(z,w)
            z2a = ffma2(zv.x, zv.x, z2a);
            z2b = ffma2(zv.y, zv.y, z2b);
            #pragma unroll
            for (int k = 0; k < 8; k++) {
                // broadcast LDS.128 (same address across all lanes)
                ulonglong2 cv = *(const ulonglong2*)(cbb + k * DD + j * 4);
                acc0[k] = ffma2(zv.x, cv.x, acc0[k]);
                acc1[k] = ffma2(zv.y, cv.y, acc1[k]);
            }
        }
    }

    // ---- per-half argmin with reference-matching quantization ----
    {
        float l0, h0, l1, h1;
        upk2(z2a, l0, h0); upk2(z2b, l1, h1);
        float z2 = (l0 + h0) + (l1 + h1);
        float best = 3.4e38f; int bi = 0;
        #pragma unroll
        for (int k = 0; k < 8; k++) {
            upk2(acc0[k], l0, h0); upk2(acc1[k], l1, h1);
            float dot = (l0 + h0) + (l1 + h1);
            float dist = (z2 - 2.0f * dot) + c2s[khalf + k];
            if (dist < best) { best = dist; bi = khalf + k; }
        }
        sdist[half][row] = best; sidx[half][row] = bi;
    }
    __syncthreads();

    // ---- combine halves (half0 wins ties == sequential first-min over k=0..15) ----
    if (t < RPB) {
        const int r = rowbase + t;
        const bool active = r < nrows;
        float d0 = sdist[0][t], d1 = sdist[1][t];
        int   bfin  = (d1 < d0) ? sidx[1][t] : sidx[0][t];
        float rloss = (d1 < d0) ? d1 : d0;
        if (!active) rloss = 0.f;
        if (active && idxp) idxp[r] = (float)bfin;
        sidx[0][t]  = bfin;      // per-thread overwrite of own slot (safe)
        sdist[0][t] = rloss;     // reuse as loss partial
    }
    __syncthreads();

    // ---- cooperative coalesced z_q write: two rows per iteration (256 threads) ----
    float4* zqg = (float4*)zq;
    const int rmax = min(RPB, nrows - rowbase);
    const int rofs = t >> 7;                    // 0 or 1
    const int col  = t & 127;
    for (int p = 0; p < RPB; p += 2) {
        int rr = p + rofs;
        if (rr < rmax) {
            int b = sidx[0][rr];                                  // broadcast per half-block
            float4 cv = *(const float4*)(sc + b * DD + col * 4);  // lane-consecutive LDS.128
            zqg[(size_t)(rowbase + rr) * (DD / 4) + col] = cv;    // coalesced STG.128
        }
    }

    // ---- deterministic block loss partial (tree over sdist[0], 128 slots) ----
    #pragma unroll
    for (int s2 = 64; s2 > 0; s2 >>= 1) {
        if (t < s2) sdist[0][t] += sdist[0][t + s2];
        __syncthreads();
    }
    if (t == 0) g_bsum[blockIdx.x] = sdist[0][0];

    // ---- last-block finalize (deterministic order; counter reset for graph replay) ----
    if (t == 0) {
        __threadfence();
        ticket = atomicAdd(&g_done, 1u);
    }
    __syncthreads();
    if (ticket == (unsigned)(nblocks - 1)) {
        float s = 0.f;
        if (t < RPB)
            for (int i = t; i < nblocks; i += RPB) s += __ldcg(&g_bsum[i]);
        if (t < RPB) sdist[1][t] = s;
        __syncthreads();
        #pragma unroll
        for (int s2 = 64; s2 > 0; s2 >>= 1) {
            if (t < s2) sdist[1][t] += sdist[1][t + s2];
            __syncthreads();
        }
        if (t == 0) {
            if (lossp) lossp[0] = sdist[1][0] * scale;
            g_done = 0;
        }
    }
}

extern "C" void kernel_launch(void* const* d_in, const int* in_sizes, int n_in,
                              void* d_out, int out_size) {
    const float* z  = (const float*)d_in[0];
    const float* cb = (const float*)d_in[1];
    int zn = in_sizes[0];          // N * D
    int N  = zn / DD;

    float* zq = (float*)d_out;
    int has_idx  = (out_size >= zn + N) ? 1 : 0;
    float* idxp  = has_idx ? ((float*)d_out + zn) : nullptr;
    float* lossp = (out_size >= zn + N + 1) ? ((float*)d_out + zn + N) : nullptr;

    int nb = (N + RPB - 1) / RPB;
    float scale = 1.25f / ((float)N * (float)DD);

    vq_fused<<<nb, TPB>>>(z, cb, zq, idxp, lossp, N, nb, scale);
}

// round 8
// speedup vs baseline: 1.2280x; 1.2280x over previous
#include <cuda_runtime.h>

#define DD   512
#define KK   16
#define RPB  128           // rows per block (== blockDim.x)
#define TPB  128
#define CH   8             // dims per staged chunk
#define NCH  (DD/CH)       // 64 chunks
#define NSTG 4             // pipeline stages (depth 3)

// ---- device scratch (no allocations allowed) ----
__device__ float g_bsum[4096];
__device__ unsigned int g_done = 0;

// ---- packed f32x2 helpers (Blackwell FFMA2) ----
__device__ __forceinline__ void upk2(unsigned long long v, float& lo, float& hi) {
    asm("mov.b64 {%0,%1}, %2;" : "=f"(lo), "=f"(hi) : "l"(v));
}
__device__ __forceinline__ unsigned long long ffma2(unsigned long long a,
                                                    unsigned long long b,
                                                    unsigned long long c) {
    unsigned long long d;
    asm("fma.rn.f32x2 %0, %1, %2, %3;" : "=l"(d) : "l"(a), "l"(b), "l"(c));
    return d;
}
__device__ __forceinline__ void cpasync16(unsigned dst, const void* src) {
    asm volatile("cp.async.cg.shared.global [%0], [%1], 16;" :: "r"(dst), "l"(src) : "memory");
}
#define CP_COMMIT() asm volatile("cp.async.commit_group;" ::: "memory")
#define CP_WAIT(n)  asm volatile("cp.async.wait_group %0;" :: "n"(n) : "memory")
#define BAR64(id)   asm volatile("bar.sync %0, 64;" :: "r"(id) : "memory")

__global__ void __launch_bounds__(TPB, 4) vq_fused(
    const float* __restrict__ z, const float* __restrict__ cb,
    float* __restrict__ zq, float* __restrict__ idxp, float* __restrict__ lossp,
    int nrows, int nblocks, float scale)
{
    __shared__ float      sc[KK * DD];            // 32 KB codebook
    __shared__ ulonglong2 zs[NSTG][2][2 * 64];    // 16 KB: [stage][pair][j*64 + rowInPair]
    __shared__ float      c2s[KK];
    __shared__ float      sdist[2][RPB];          // per-half best dist (reused for loss)
    __shared__ int        sidx[2][RPB];           // per-half best idx
    __shared__ unsigned int ticket;

    const int t = threadIdx.x;
    const int w = t >> 5, lane = t & 31;
    const int p     = w >> 1;                     // warp pair (rows p*64 .. p*64+63)
    const int h     = w & 1;                      // k-half this warp owns
    const int khalf = h * 8;
    const int rowbase = blockIdx.x * RPB;

    const unsigned zs_sa = (unsigned)__cvta_generic_to_shared(zs);

    // ---- pair-private staging roles: tp in [0,64) ----
    const int tp = t & 63;
    const int jj = tp & 1;                        // which float4 of the 8-dim chunk
    const int rl = tp >> 1;                       // 0..31 -> rows rl, rl+32 (within pair)
    const int lastrow = nrows - 1;

    int gr0 = rowbase + p * 64 + rl;       if (gr0 > lastrow) gr0 = lastrow;
    int gr1 = rowbase + p * 64 + rl + 32;  if (gr1 > lastrow) gr1 = lastrow;
    const char* src0 = (const char*)z + ((size_t)gr0 * (DD / 4) + jj) * 16;
    const char* src1 = (const char*)z + ((size_t)gr1 * (DD / 4) + jj) * 16;
    // smem dst for (stage s): zs_sa + (s*256 + p*128 + jj*64 + rw) * 16
    const unsigned dst0 = zs_sa + (unsigned)((p * 128 + jj * 64 + rl) * 16);
    const unsigned dst1 = dst0 + 32 * 16;

    // issue chunk c into stage s (2 x 16B per thread), then commit
    #define ISSUE(c, s) do {                                              \
        cpasync16(dst0 + (unsigned)((s) * 4096), src0 + (size_t)(c) * 32);\
        cpasync16(dst1 + (unsigned)((s) * 4096), src1 + (size_t)(c) * 32);\
        CP_COMMIT();                                                      \
    } while (0)

    // ---- prologue: issue chunks 0..2 ----
    ISSUE(0, 0);
    ISSUE(1, 1);
    ISSUE(2, 2);

    // ---- stage codebook (coalesced float4) ----
    for (int i = t; i < KK * DD / 4; i += TPB)
        ((float4*)sc)[i] = ((const float4*)cb)[i];
    __syncthreads();

    // ---- codebook squared norms (identical per-k arithmetic as before) ----
    #pragma unroll
    for (int kk = 0; kk < 4; kk++) {
        int k = w * 4 + kk;
        float s = 0.f;
        for (int j = lane; j < DD; j += 32) {
            float v = sc[k * DD + j];
            s = fmaf(v, v, s);
        }
        #pragma unroll
        for (int o = 16; o; o >>= 1) s += __shfl_xor_sync(0xffffffffu, s, o);
        if (lane == 0) c2s[k] = s;
    }
    __syncthreads();

    // ---- single-chain accumulators: 8 k for rows (p*64+lane) and (+32) ----
    unsigned long long acc0[8], acc1[8];
    #pragma unroll
    for (int k = 0; k < 8; k++) { acc0[k] = 0ull; acc1[k] = 0ull; }
    unsigned long long z2r0 = 0ull, z2r1 = 0ull;

    for (int c = 0; c < NCH; c++) {
        // drain so chunk c is resident (pending = {c, c+1, c+2} at steady state)
        if      (c <= NCH - 3) CP_WAIT(2);
        else if (c == NCH - 2) CP_WAIT(1);
        else                   CP_WAIT(0);
        BAR64(1 + p);                       // pair barrier: chunk c visible; stage (c+3)&3 free

        if (c + 3 < NCH) ISSUE(c + 3, (c + 3) & 3);

        const ulonglong2* zb = zs[c & 3][p];
        const float* cbb = sc + (khalf * DD + c * CH);

        #pragma unroll
        for (int j = 0; j < CH / 8 * 2; j++) {          // 2 float4 groups
            ulonglong2 zv0 = zb[j * 64 + lane];         // row p*64+lane
            ulonglong2 zv1 = zb[j * 64 + lane + 32];    // row p*64+lane+32
            z2r0 = ffma2(zv0.x, zv0.x, z2r0);  z2r0 = ffma2(zv0.y, zv0.y, z2r0);
            z2r1 = ffma2(zv1.x, zv1.x, z2r1);  z2r1 = ffma2(zv1.y, zv1.y, z2r1);
            #pragma unroll
            for (int k = 0; k < 8; k++) {
                // broadcast LDS.128 (same address across lanes), feeds both rows
                ulonglong2 cv = *(const ulonglong2*)(cbb + k * DD + j * 4);
                acc0[k] = ffma2(zv0.x, cv.x, acc0[k]);
                acc0[k] = ffma2(zv0.y, cv.y, acc0[k]);
                acc1[k] = ffma2(zv1.x, cv.x, acc1[k]);
                acc1[k] = ffma2(zv1.y, cv.y, acc1[k]);
            }
        }
    }

    // ---- per-half argmin with reference-matching quantization ----
    {
        float lo, hi;
        upk2(z2r0, lo, hi);
        float z2 = lo + hi;
        float best = 3.4e38f; int bi = 0;
        #pragma unroll
        for (int k = 0; k < 8; k++) {
            upk2(acc0[k], lo, hi);
            float dot = lo + hi;
            float dist = (z2 - 2.0f * dot) + c2s[khalf + k];
            if (dist < best) { best = dist; bi = khalf + k; }
        }
        sdist[h][p * 64 + lane] = best; sidx[h][p * 64 + lane] = bi;
    }
    {
        float lo, hi;
        upk2(z2r1, lo, hi);
        float z2 = lo + hi;
        float best = 3.4e38f; int bi = 0;
        #pragma unroll
        for (int k = 0; k < 8; k++) {
            upk2(acc1[k], lo, hi);
            float dot = lo + hi;
            float dist = (z2 - 2.0f * dot) + c2s[khalf + k];
            if (dist < best) { best = dist; bi = khalf + k; }
        }
        sdist[h][p * 64 + lane + 32] = best; sidx[h][p * 64 + lane + 32] = bi;
    }
    __syncthreads();

    // ---- combine halves (half0 wins ties == sequential first-min over k=0..15) ----
    {
        const int r = rowbase + t;
        const bool active = r < nrows;
        float d0 = sdist[0][t], d1 = sdist[1][t];
        int   bfin  = (d1 < d0) ? sidx[1][t] : sidx[0][t];
        float rloss = (d1 < d0) ? d1 : d0;
        if (!active) rloss = 0.f;
        if (active && idxp) idxp[r] = (float)bfin;
        sidx[0][t]  = bfin;
        sdist[0][t] = rloss;
    }
    __syncthreads();

    // ---- cooperative coalesced z_q write: one full row per iteration ----
    float4* zqg = (float4*)zq;
    const int rmax = min(RPB, nrows - rowbase);
    for (int rr = 0; rr < rmax; rr++) {
        int b = sidx[0][rr];                                // broadcast
        float4 cv = *(const float4*)(sc + b * DD + t * 4);  // lane-consecutive LDS.128
        zqg[(size_t)(rowbase + rr) * (DD / 4) + t] = cv;    // coalesced STG.128
    }

    // ---- deterministic block loss partial ----
    #pragma unroll
    for (int s2 = 64; s2 > 0; s2 >>= 1) {
        if (t < s2) sdist[0][t] += sdist[0][t + s2];
        __syncthreads();
    }
    if (t == 0) g_bsum[blockIdx.x] = sdist[0][0];

    // ---- last-block finalize (deterministic order; counter reset for graph replay) ----
    if (t == 0) {
        __threadfence();
        ticket = atomicAdd(&g_done, 1u);
    }
    __syncthreads();
    if (ticket == (unsigned)(nblocks - 1)) {
        float s = 0.f;
        for (int i = t; i < nblocks; i += TPB) s += __ldcg(&g_bsum[i]);
        sdist[1][t] = s;
        __syncthreads();
        #pragma unroll
        for (int s2 = 64; s2 > 0; s2 >>= 1) {
            if (t < s2) sdist[1][t] += sdist[1][t + s2];
            __syncthreads();
        }
        if (t == 0) {
            if (lossp) lossp[0] = sdist[1][0] * scale;
            g_done = 0;
        }
    }
    #undef ISSUE
}

extern "C" void kernel_launch(void* const* d_in, const int* in_sizes, int n_in,
                              void* d_out, int out_size) {
    const float* z  = (const float*)d_in[0];
    const float* cb = (const float*)d_in[1];
    int zn = in_sizes[0];          // N * D
    int N  = zn / DD;

    float* zq = (float*)d_out;
    int has_idx  = (out_size >= zn + N) ? 1 : 0;
    float* idxp  = has_idx ? ((float*)d_out + zn) : nullptr;
    float* lossp = (out_size >= zn + N + 1) ? ((float*)d_out + zn + N) : nullptr;

    int nb = (N + RPB - 1) / RPB;
    float scale = 1.25f / ((float)N * (float)DD);

    vq_fused<<<nb, TPB>>>(z, cb, zq, idxp, lossp, N, nb, scale);
}

// round 9
// speedup vs baseline: 1.6189x; 1.3182x over previous
#include <cuda_runtime.h>

#define DD   512
#define KK   16
#define TPB  256           // 8 warps; warp owns 32 rows, all 16 k
#define RPB  256           // rows per block
#define CH   32            // dims per chunk = 128B per row = one sector
#define NCH  (DD/CH)       // 16 chunks

// ---- dynamic smem layout (bytes) ----
#define SM_CB     0                       // codebook: 16*512*4 = 32768
#define SM_ZSTG   32768                   // staging: 2 stages * 8 warps * 4096 = 65536
#define SM_SDIST  98304                   // 256 * 4
#define SM_SIDX   99328                   // 256 * 4
#define SM_C2S    100352                  // 16 * 4
#define SM_TICKET 100416                  // 4
#define SM_TOTAL  100424

// ---- device scratch (no allocations allowed) ----
__device__ float g_bsum[4096];
__device__ unsigned int g_done = 0;

// ---- packed f32x2 helpers (Blackwell FFMA2) ----
__device__ __forceinline__ void upk2(unsigned long long v, float& lo, float& hi) {
    asm("mov.b64 {%0,%1}, %2;" : "=f"(lo), "=f"(hi) : "l"(v));
}
__device__ __forceinline__ unsigned long long ffma2(unsigned long long a,
                                                    unsigned long long b,
                                                    unsigned long long c) {
    unsigned long long d;
    asm("fma.rn.f32x2 %0, %1, %2, %3;" : "=l"(d) : "l"(a), "l"(b), "l"(c));
    return d;
}
__device__ __forceinline__ void cpasync16(unsigned dst, const void* src) {
    asm volatile("cp.async.cg.shared.global [%0], [%1], 16;" :: "r"(dst), "l"(src) : "memory");
}
#define CP_COMMIT() asm volatile("cp.async.commit_group;" ::: "memory")
#define CP_WAIT(n)  asm volatile("cp.async.wait_group %0;" :: "n"(n) : "memory")

__global__ void __launch_bounds__(TPB, 2) vq_fused(
    const float* __restrict__ z, const float* __restrict__ cb,
    float* __restrict__ zq, float* __restrict__ idxp, float* __restrict__ lossp,
    int nrows, int nblocks, float scale)
{
    extern __shared__ char smem[];
    float*        sc     = (float*)(smem + SM_CB);
    float*        sdist  = (float*)(smem + SM_SDIST);
    int*          sidx   = (int*)(smem + SM_SIDX);
    float*        c2s    = (float*)(smem + SM_C2S);
    unsigned int* ticket = (unsigned int*)(smem + SM_TICKET);

    const int t = threadIdx.x;
    const int w = t >> 5, lane = t & 31;
    const int rowbase = blockIdx.x * RPB;
    const int lastrow = nrows - 1;

    const unsigned smem_sa = (unsigned)__cvta_generic_to_shared(smem);
    // staging base for (stage s, warp w): SM_ZSTG + (s*8 + w)*4096
    const unsigned stg_w = smem_sa + SM_ZSTG + (unsigned)(w * 4096);
    const int swz = lane & 7;                     // this lane's read swizzle

    // cp.async roles: instruction i stages rows i*4 + (lane>>3), piece jj = lane&7
    const int srow = lane >> 3;                   // 0..3
    const int sjj  = lane & 7;                    // 0..7

    // issue chunk c into stage s: 8 cp.async of 16B, 4 rows each, full 128B segments
    #define ISSUE(c, s) do {                                                        \
        _Pragma("unroll")                                                           \
        for (int i = 0; i < 8; i++) {                                               \
            int rr = i * 4 + srow;                                                  \
            int gr = rowbase + w * 32 + rr; if (gr > lastrow) gr = lastrow;         \
            const char* src = (const char*)z + (size_t)gr * (DD * 4)                \
                              + (size_t)(c) * (CH * 4) + sjj * 16;                  \
            unsigned dst = stg_w + (unsigned)((s) * 32768)                          \
                           + (unsigned)(rr * 128 + ((sjj ^ (rr & 7)) << 4));        \
            cpasync16(dst, src);                                                    \
        }                                                                           \
        CP_COMMIT();                                                                \
    } while (0)

    // ---- prologue: stage chunk 0 ----
    ISSUE(0, 0);

    // ---- stage codebook (coalesced float4) ----
    for (int i = t; i < KK * DD / 4; i += TPB)
        ((float4*)sc)[i] = ((const float4*)cb)[i];
    __syncthreads();

    // ---- codebook squared norms (identical per-k arithmetic as before) ----
    #pragma unroll
    for (int kk = 0; kk < 2; kk++) {
        int k = w * 2 + kk;
        float s = 0.f;
        for (int j = lane; j < DD; j += 32) {
            float v = sc[k * DD + j];
            s = fmaf(v, v, s);
        }
        #pragma unroll
        for (int o = 16; o; o >>= 1) s += __shfl_xor_sync(0xffffffffu, s, o);
        if (lane == 0) c2s[k] = s;
    }
    __syncthreads();                      // c2s + sc visible; no block syncs until epilogue

    // ---- accumulators: one chain per k, bit-identical order to R8 ----
    unsigned long long acc[KK];
    #pragma unroll
    for (int k = 0; k < KK; k++) acc[k] = 0ull;
    unsigned long long z2 = 0ull;

    const char* stg_rd = (const char*)smem + SM_ZSTG + w * 4096 + lane * 128;

    for (int c = 0; c < NCH; c++) {
        if (c + 1 < NCH) {
            ISSUE(c + 1, (c + 1) & 1);    // overlaps chunk c wait + compute
            CP_WAIT(1);                   // chunk c complete, c+1 in flight
        } else {
            CP_WAIT(0);
        }
        __syncwarp();                     // cross-lane staging visibility (warp-local)

        const char* rb = stg_rd + (c & 1) * 32768;
        const float* cbb = sc + c * CH;

        #pragma unroll
        for (int jg = 0; jg < 8; jg++) {  // 8 x 4-dim groups
            ulonglong2 zv = *(const ulonglong2*)(rb + ((jg ^ swz) << 4));
            z2 = ffma2(zv.x, zv.x, z2);
            z2 = ffma2(zv.y, zv.y, z2);
            #pragma unroll
            for (int k = 0; k < KK; k++) {
                // broadcast LDS.128 (same address across lanes)
                ulonglong2 cv = *(const ulonglong2*)(cbb + k * DD + jg * 4);
                acc[k] = ffma2(zv.x, cv.x, acc[k]);
                acc[k] = ffma2(zv.y, cv.y, acc[k]);
            }
        }
        __syncwarp();                     // all lanes done reading before next overwrite
    }

    // ---- argmin with reference-matching quantization (seq k=0..15, strict <) ----
    {
        float lo, hi;
        upk2(z2, lo, hi);
        float z2s = lo + hi;
        float best = 3.4e38f; int bi = 0;
        #pragma unroll
        for (int k = 0; k < KK; k++) {
            upk2(acc[k], lo, hi);
            float dot = lo + hi;
            float dist = (z2s - 2.0f * dot) + c2s[k];
            if (dist < best) { best = dist; bi = k; }
        }
        const int r = rowbase + t;        // thread t's row == block-local t
        const bool active = r < nrows;
        sdist[t] = active ? best : 0.f;
        sidx[t]  = bi;
        if (active && idxp) idxp[r] = (float)bi;
    }
    __syncthreads();

    // ---- cooperative coalesced z_q write: two rows per iteration ----
    float4* zqg = (float4*)zq;
    const int rmax = min(RPB, nrows - rowbase);
    const int rofs = t >> 7;              // 0 or 1
    const int col  = t & 127;
    for (int p = 0; p < RPB; p += 2) {
        int rr = p + rofs;
        if (rr < rmax) {
            int b = sidx[rr];                                   // broadcast
            float4 cv = *(const float4*)(sc + b * DD + col * 4);
            zqg[(size_t)(rowbase + rr) * (DD / 4) + col] = cv;  // coalesced STG.128
        }
    }

    // ---- deterministic block loss partial (tree over 256) ----
    #pragma unroll
    for (int s2 = 128; s2 > 0; s2 >>= 1) {
        if (t < s2) sdist[t] += sdist[t + s2];
        __syncthreads();
    }
    if (t == 0) g_bsum[blockIdx.x] = sdist[0];

    // ---- last-block finalize (deterministic order; counter reset for graph replay) ----
    if (t == 0) {
        __threadfence();
        ticket[0] = atomicAdd(&g_done, 1u);
    }
    __syncthreads();
    if (ticket[0] == (unsigned)(nblocks - 1)) {
        float s = 0.f;
        for (int i = t; i < nblocks; i += TPB) s += __ldcg(&g_bsum[i]);
        sdist[t] = s;
        __syncthreads();
        #pragma unroll
        for (int s2 = 128; s2 > 0; s2 >>= 1) {
            if (t < s2) sdist[t] += sdist[t + s2];
            __syncthreads();
        }
        if (t == 0) {
            if (lossp) lossp[0] = sdist[0] * scale;
            g_done = 0;
        }
    }
    #undef ISSUE
}

extern "C" void kernel_launch(void* const* d_in, const int* in_sizes, int n_in,
                              void* d_out, int out_size) {
    const float* z  = (const float*)d_in[0];
    const float* cb = (const float*)d_in[1];
    int zn = in_sizes[0];          // N * D
    int N  = zn / DD;

    float* zq = (float*)d_out;
    int has_idx  = (out_size >= zn + N) ? 1 : 0;
    float* idxp  = has_idx ? ((float*)d_out + zn) : nullptr;
    float* lossp = (out_size >= zn + N + 1) ? ((float*)d_out + zn + N) : nullptr;

    int nb = (N + RPB - 1) / RPB;
    float scale = 1.25f / ((float)N * (float)DD);

    cudaFuncSetAttribute(vq_fused, cudaFuncAttributeMaxDynamicSharedMemorySize, SM_TOTAL);
    vq_fused<<<nb, TPB, SM_TOTAL>>>(z, cb, zq, idxp, lossp, N, nb, scale);
}